// round 1
// baseline (speedup 1.0000x reference)
#include <cuda_runtime.h>
#include <math.h>

#define NB   4
#define NTOK 4096
#define NC   192
#define NHD  64
#define MAXM 3969

static const float ATT_SCALE = 0.07216878364870323f; // 192^-0.5

// ---------------- scratch (__device__ globals: allocation-free rule) ----------
__device__ float g_ximg[NB * NC * NTOK + 128];          // (B,C,4096) + OOB pad
__device__ float g_q[NB * NTOK * NC];                   // q projection
__device__ float g_wr[64 * NC * NC];                    // reordered conv weights
__device__ float g_t[2 * NB * MAXM * NC];               // conv partials / t
__device__ float g_kv[NB * MAXM * 128];                 // k (0:64) v (64:128)
__device__ float g_vp[NB * MAXM * 64];                  // v + depthwise conv
__device__ float g_S[(size_t)NB * NTOK * MAXM];         // attention logits/probs
__device__ float g_xcat[NB * NTOK * NC];                // concat of branch outputs

// ---------------- helpers ------------------------------------------------------
__device__ __forceinline__ float warpSum(float v) {
#pragma unroll
    for (int o = 16; o; o >>= 1) v += __shfl_xor_sync(0xffffffffu, v, o);
    return v;
}
__device__ __forceinline__ float warpMax(float v) {
#pragma unroll
    for (int o = 16; o; o >>= 1) v = fmaxf(v, __shfl_xor_sync(0xffffffffu, v, o));
    return v;
}

// ---------------- transpose x (B,N,C) -> (B,C,N) -------------------------------
__global__ void transpose_kernel(const float* __restrict__ x, float* __restrict__ ximg) {
    __shared__ float tile[32][33];
    int b = blockIdx.z;
    int p0 = blockIdx.x << 5, c0 = blockIdx.y << 5;
    int tx = threadIdx.x, ty = threadIdx.y;
#pragma unroll
    for (int i = ty; i < 32; i += 8)
        tile[i][tx] = x[((size_t)b * NTOK + p0 + i) * NC + c0 + tx];
    __syncthreads();
#pragma unroll
    for (int i = ty; i < 32; i += 8)
        ximg[((size_t)b * NC + c0 + i) * NTOK + p0 + tx] = tile[tx][i];
}

// ---------------- reorder sr weights (co,ci,ky,kx) -> [tap][ci][co] ------------
__global__ void reorder_w_kernel(const float* __restrict__ w, float* __restrict__ wr, int k2) {
    int idx = blockIdx.x * 256 + threadIdx.x;
    int total = k2 * NC * NC;
    if (idx >= total) return;
    int co = idx % NC;
    int ci = (idx / NC) % NC;
    int tap = idx / (NC * NC);
    wr[idx] = w[((size_t)co * NC + ci) * k2 + tap];
}

// ---------------- stride-1 VALID conv 192->192 as shifted rank-updates ---------
// grid: (side, B, 2 ci-halves); block 256. Output tile: 192 co x 64 px (one oy row).
__global__ void __launch_bounds__(256) sr_conv_kernel(
    const float* __restrict__ ximg, const float* __restrict__ wr,
    const float* __restrict__ bias, float* __restrict__ out,
    int k, int side, int m)
{
    __shared__ float Wsm[16][192];
    __shared__ float Xsm[16][64];
    const size_t PART = (size_t)NB * MAXM * NC;
    int tid = threadIdx.x;
    int pxg = tid & 7;    // 8 px-groups of 8 px
    int cog = tid >> 3;   // 32 co-groups of 6 co
    int oy = blockIdx.x;
    int b  = blockIdx.y;
    int ci0 = blockIdx.z * 96;
    out += (size_t)blockIdx.z * PART;

    float acc[6][8];
#pragma unroll
    for (int i = 0; i < 6; i++)
#pragma unroll
        for (int j = 0; j < 8; j++) acc[i][j] = 0.f;

    const float* xb = ximg + (size_t)b * NC * NTOK;
    int k2 = k * k;
    for (int tap = 0; tap < k2; tap++) {
        int dy = tap / k, dx = tap - dy * k;
        const float* xrow = xb + (oy + dy) * 64 + dx;
        const float* wtap = wr + (size_t)tap * NC * NC;
        for (int cc = 0; cc < 96; cc += 16) {
            int cbase = ci0 + cc;
            __syncthreads();
#pragma unroll
            for (int j = 0; j < 12; j++) {
                int idx = tid + j * 256;
                int co = idx % 192, ci = idx / 192;
                Wsm[ci][co] = wtap[(size_t)(cbase + ci) * 192 + co];
            }
#pragma unroll
            for (int j = 0; j < 4; j++) {
                int idx = tid + j * 256;
                int px = idx & 63, ci = idx >> 6;
                Xsm[ci][px] = xrow[(size_t)(cbase + ci) * NTOK + px];
            }
            __syncthreads();
#pragma unroll
            for (int ci = 0; ci < 16; ci++) {
                float xr[8];
#pragma unroll
                for (int j = 0; j < 8; j++) xr[j] = Xsm[ci][pxg * 8 + j];
#pragma unroll
                for (int i = 0; i < 6; i++) {
                    float wv = Wsm[ci][cog * 6 + i];
#pragma unroll
                    for (int j = 0; j < 8; j++) acc[i][j] = fmaf(wv, xr[j], acc[i][j]);
                }
            }
        }
    }
    size_t base = ((size_t)b * m + (size_t)oy * side) * NC;
#pragma unroll
    for (int j = 0; j < 8; j++) {
        int ox = pxg * 8 + j;
        if (ox < side) {
            float* op = out + base + (size_t)ox * NC + cog * 6;
#pragma unroll
            for (int i = 0; i < 6; i++) {
                float bb = (ci0 == 0) ? bias[cog * 6 + i] : 0.f;
                op[i] = acc[i][j] + bb;
            }
        }
    }
}

// ---------------- LayerNorm + exact GELU over C=192 (sums conv partials) -------
__global__ void ln_gelu_kernel(float* __restrict__ t, const float* __restrict__ g,
                               const float* __restrict__ bb) {
    const size_t PART = (size_t)NB * MAXM * NC;
    size_t row = blockIdx.x;
    int tid = threadIdx.x;
    float v = t[row * NC + tid] + t[PART + row * NC + tid];
    __shared__ float sm[6];
    int lane = tid & 31, w = tid >> 5;
    float s = warpSum(v);
    if (lane == 0) sm[w] = s;
    __syncthreads();
    float mean = 0.f;
#pragma unroll
    for (int i = 0; i < 6; i++) mean += sm[i];
    mean *= (1.0f / 192.0f);
    float d = v - mean;
    __syncthreads();
    s = warpSum(d * d);
    if (lane == 0) sm[w] = s;
    __syncthreads();
    float var = 0.f;
#pragma unroll
    for (int i = 0; i < 6; i++) var += sm[i];
    var *= (1.0f / 192.0f);
    float y = d * rsqrtf(var + 1e-5f) * g[tid] + bb[tid];
    t[row * NC + tid] = y * normcdff(y);
}

// ---------------- generic NT GEMM: C = scale*(A @ W^T) + bias ------------------
// A: MxK row-major (lda), W: NxK row-major (ldw). Tile 128x64xBK16, 256 thr.
__global__ void __launch_bounds__(256) gemm_nt(
    const float* __restrict__ A, long long sA, int lda,
    const float* __restrict__ W, long long sW, int ldw,
    const float* __restrict__ bias,
    float* __restrict__ C, long long sC, int ldc,
    int M, int Nn, int K, float scale)
{
    __shared__ float As[16][132];
    __shared__ float Ws[16][68];
    int bz = blockIdx.z;
    const float* Ab = A + sA * bz;
    const float* Wb = W + sW * bz;
    float* Cb = C + sC * bz;
    int n0 = blockIdx.x * 64, m0 = blockIdx.y * 128;
    int tid = threadIdx.x;
    int tx = tid & 15, ty = tid >> 4;
    float acc[8][4];
#pragma unroll
    for (int i = 0; i < 8; i++)
#pragma unroll
        for (int j = 0; j < 4; j++) acc[i][j] = 0.f;

    for (int k0 = 0; k0 < K; k0 += 16) {
#pragma unroll
        for (int j = 0; j < 8; j++) {
            int idx = tid + j * 256;
            int kk = idx & 15, mm = idx >> 4;
            int gm = m0 + mm, gk = k0 + kk;
            As[kk][mm] = (gm < M && gk < K) ? Ab[(size_t)gm * lda + gk] : 0.f;
        }
#pragma unroll
        for (int j = 0; j < 4; j++) {
            int idx = tid + j * 256;
            int kk = idx & 15, nn = idx >> 4;
            int gn = n0 + nn, gk = k0 + kk;
            Ws[kk][nn] = (gn < Nn && gk < K) ? Wb[(size_t)gn * ldw + gk] : 0.f;
        }
        __syncthreads();
#pragma unroll
        for (int kk = 0; kk < 16; kk++) {
            float a[8], w[4];
#pragma unroll
            for (int i = 0; i < 8; i++) a[i] = As[kk][ty * 8 + i];
#pragma unroll
            for (int j = 0; j < 4; j++) w[j] = Ws[kk][tx * 4 + j];
#pragma unroll
            for (int i = 0; i < 8; i++)
#pragma unroll
                for (int j = 0; j < 4; j++) acc[i][j] = fmaf(a[i], w[j], acc[i][j]);
        }
        __syncthreads();
    }
#pragma unroll
    for (int i = 0; i < 8; i++) {
        int gm = m0 + ty * 8 + i;
        if (gm >= M) continue;
#pragma unroll
        for (int j = 0; j < 4; j++) {
            int gn = n0 + tx * 4 + j;
            if (gn < Nn) {
                float v = acc[i][j] * scale;
                if (bias) v += bias[gn];
                Cb[(size_t)gm * ldc + gn] = v;
            }
        }
    }
}

// ---------------- generic NN GEMM: C = A(MxK) @ Bm(KxN) ------------------------
__global__ void __launch_bounds__(256) gemm_nn(
    const float* __restrict__ A, long long sA, int lda,
    const float* __restrict__ Bm, long long sB, int ldb,
    float* __restrict__ C, long long sC, int ldc,
    int M, int Nn, int K)
{
    __shared__ float As[16][132];
    __shared__ float Ws[16][68];
    int bz = blockIdx.z;
    const float* Ab = A + sA * bz;
    const float* Bb = Bm + sB * bz;
    float* Cb = C + sC * bz;
    int n0 = blockIdx.x * 64, m0 = blockIdx.y * 128;
    int tid = threadIdx.x;
    int tx = tid & 15, ty = tid >> 4;
    float acc[8][4];
#pragma unroll
    for (int i = 0; i < 8; i++)
#pragma unroll
        for (int j = 0; j < 4; j++) acc[i][j] = 0.f;

    for (int k0 = 0; k0 < K; k0 += 16) {
#pragma unroll
        for (int j = 0; j < 8; j++) {
            int idx = tid + j * 256;
            int kk = idx & 15, mm = idx >> 4;
            int gm = m0 + mm, gk = k0 + kk;
            As[kk][mm] = (gm < M && gk < K) ? Ab[(size_t)gm * lda + gk] : 0.f;
        }
#pragma unroll
        for (int j = 0; j < 4; j++) {
            int idx = tid + j * 256;
            int nn = idx & 63, kk = idx >> 6;
            int gn = n0 + nn, gk = k0 + kk;
            Ws[kk][nn] = (gk < K && gn < Nn) ? Bb[(size_t)gk * ldb + gn] : 0.f;
        }
        __syncthreads();
#pragma unroll
        for (int kk = 0; kk < 16; kk++) {
            float a[8], w[4];
#pragma unroll
            for (int i = 0; i < 8; i++) a[i] = As[kk][ty * 8 + i];
#pragma unroll
            for (int j = 0; j < 4; j++) w[j] = Ws[kk][tx * 4 + j];
#pragma unroll
            for (int i = 0; i < 8; i++)
#pragma unroll
                for (int j = 0; j < 4; j++) acc[i][j] = fmaf(a[i], w[j], acc[i][j]);
        }
        __syncthreads();
    }
#pragma unroll
    for (int i = 0; i < 8; i++) {
        int gm = m0 + ty * 8 + i;
        if (gm >= M) continue;
#pragma unroll
        for (int j = 0; j < 4; j++) {
            int gn = n0 + tx * 4 + j;
            if (gn < Nn) Cb[(size_t)gm * ldc + gn] = acc[i][j];
        }
    }
}

// ---------------- depthwise 3x3 (same pad) on v, residual add ------------------
__global__ void dwconv_kernel(const float* __restrict__ kv, const float* __restrict__ lw,
                              const float* __restrict__ lb, float* __restrict__ vp,
                              int side, int m)
{
    long long idx = (long long)blockIdx.x * 256 + threadIdx.x;
    long long total = (long long)NB * m * 64;
    if (idx >= total) return;
    int hd = (int)(idx & 63);
    long long pm = idx >> 6;
    int p = (int)(pm % m);
    int b = (int)(pm / m);
    int y = p / side, x = p % side;
    const float* vbase = kv + (size_t)b * m * 128 + 64 + hd;
    float s = lb[hd];
#pragma unroll
    for (int dy = 0; dy < 3; dy++) {
        int yy = y + dy - 1;
        if (yy < 0 || yy >= side) continue;
#pragma unroll
        for (int dx = 0; dx < 3; dx++) {
            int xx = x + dx - 1;
            if (xx < 0 || xx >= side) continue;
            s += lw[hd * 9 + dy * 3 + dx] * vbase[(size_t)(yy * side + xx) * 128];
        }
    }
    vp[idx] = vbase[(size_t)p * 128] + s;
}

// ---------------- row softmax over m -------------------------------------------
__global__ void softmax_kernel(float* __restrict__ S, int mcols) {
    size_t row = blockIdx.x;
    float* r = S + row * (size_t)mcols;
    int tid = threadIdx.x;
    float lv[16];
    int cnt = 0;
    float mx = -1e30f;
    for (int j = tid; j < mcols; j += 256) {
        float v = r[j];
        lv[cnt++] = v;
        if (v > mx) mx = v;
    }
    __shared__ float sm[8];
    int lane = tid & 31, w = tid >> 5;
    float tmp = warpMax(mx);
    if (lane == 0) sm[w] = tmp;
    __syncthreads();
    mx = -1e30f;
#pragma unroll
    for (int i = 0; i < 8; i++) mx = fmaxf(mx, sm[i]);
    float sum = 0.f;
    for (int i = 0; i < cnt; i++) {
        float e = __expf(lv[i] - mx);
        lv[i] = e;
        sum += e;
    }
    __syncthreads();
    tmp = warpSum(sum);
    if (lane == 0) sm[w] = tmp;
    __syncthreads();
    sum = 0.f;
#pragma unroll
    for (int i = 0; i < 8; i++) sum += sm[i];
    float inv = 1.f / sum;
    cnt = 0;
    for (int j = tid; j < mcols; j += 256) r[j] = lv[cnt++] * inv;
}

// ---------------- host orchestration -------------------------------------------
extern "C" void kernel_launch(void* const* d_in, const int* in_sizes, int n_in,
                              void* d_out, int out_size)
{
    (void)in_sizes; (void)n_in; (void)out_size;
    const float* x    = (const float*)d_in[0];
    const float* q_w  = (const float*)d_in[1];
    const float* q_b  = (const float*)d_in[2];
    const float* kv_w = (const float*)d_in[3];
    const float* kv_b = (const float*)d_in[4];
    const float* sr_w[3] = {(const float*)d_in[5], (const float*)d_in[7], (const float*)d_in[9]};
    const float* sr_b[3] = {(const float*)d_in[6], (const float*)d_in[8], (const float*)d_in[10]};
    const float* ln_g[3] = {(const float*)d_in[11], (const float*)d_in[13], (const float*)d_in[15]};
    const float* ln_b[3] = {(const float*)d_in[12], (const float*)d_in[14], (const float*)d_in[16]};
    const float* lc_w[3] = {(const float*)d_in[17], (const float*)d_in[19], (const float*)d_in[21]};
    const float* lc_b[3] = {(const float*)d_in[18], (const float*)d_in[20], (const float*)d_in[22]};
    const float* nn1_w = (const float*)d_in[23];
    const float* nn1_b = (const float*)d_in[24];
    float* out = (float*)d_out;

    float *p_ximg, *p_q, *p_wr, *p_t, *p_kv, *p_vp, *p_S, *p_xcat;
    cudaGetSymbolAddress((void**)&p_ximg, g_ximg);
    cudaGetSymbolAddress((void**)&p_q,    g_q);
    cudaGetSymbolAddress((void**)&p_wr,   g_wr);
    cudaGetSymbolAddress((void**)&p_t,    g_t);
    cudaGetSymbolAddress((void**)&p_kv,   g_kv);
    cudaGetSymbolAddress((void**)&p_vp,   g_vp);
    cudaGetSymbolAddress((void**)&p_S,    g_S);
    cudaGetSymbolAddress((void**)&p_xcat, g_xcat);

    // x -> (B, C, 4096)
    transpose_kernel<<<dim3(128, 6, NB), dim3(32, 8)>>>(x, p_ximg);

    // q projection: (16384,192) = x @ q_w^T + q_b
    gemm_nt<<<dim3(3, 128, 1), 256>>>(x, 0, NC, q_w, 0, NC, q_b,
                                      p_q, 0, NC, NB * NTOK, NC, NC, 1.f);

    const int KS[3] = {8, 4, 2};
    for (int h = 0; h < 3; h++) {
        int k = KS[h];
        int side = 64 - k + 1;
        int m = side * side;
        int k2 = k * k;

        reorder_w_kernel<<<(k2 * NC * NC + 255) / 256, 256>>>(sr_w[h], p_wr, k2);
        sr_conv_kernel<<<dim3(side, NB, 2), 256>>>(p_ximg, p_wr, sr_b[h], p_t, k, side, m);
        ln_gelu_kernel<<<NB * m, 192>>>(p_t, ln_g[h], ln_b[h]);

        // kv = t @ kv_w^T + kv_b (first 128 output cols: k then v)
        gemm_nt<<<dim3(2, (NB * m + 127) / 128, 1), 256>>>(
            p_t, 0, NC, kv_w, 0, NC, kv_b, p_kv, 0, 128, NB * m, 128, NC, 1.f);

        // v' = v + depthwise3x3(v)
        dwconv_kernel<<<(int)(((long long)NB * m * 64 + 255) / 256), 256>>>(
            p_kv, lc_w[h], lc_b[h], p_vp, side, m);

        // S = SCALE * q_h @ k^T  (batched over B)
        gemm_nt<<<dim3((m + 63) / 64, NTOK / 128, NB), 256>>>(
            p_q + h * 64, (long long)NTOK * NC, NC,
            p_kv, (long long)m * 128, 128, nullptr,
            p_S, (long long)NTOK * m, m, NTOK, m, 64, ATT_SCALE);

        softmax_kernel<<<NB * NTOK, 256>>>(p_S, m);

        // xcat[:, h*64:(h+1)*64] = P @ v'
        gemm_nn<<<dim3(1, NTOK / 128, NB), 256>>>(
            p_S, (long long)NTOK * m, m,
            p_vp, (long long)m * 64, 64,
            p_xcat + h * 64, (long long)NTOK * NC, NC, NTOK, 64, m);
    }

    // final projection
    gemm_nt<<<dim3(3, 128, 1), 256>>>(p_xcat, 0, NC, nn1_w, 0, NC, nn1_b,
                                      out, 0, NC, NB * NTOK, NC, NC, 1.f);
}